// round 2
// baseline (speedup 1.0000x reference)
#include <cuda_runtime.h>
#include <math.h>

#define NFR 5
#define BB  8
#define CC  64
#define HW  16384
#define KK  (NFR*CC)   /* 320 */

// Scratch (no allocations allowed): origin buffer 33.5MB, stats, folded weights.
__device__ float g_origin[(size_t)BB*CC*HW];
__device__ float g_stats[BB*CC*12];
__device__ float g_A[BB*NFR*CC];

__device__ __forceinline__ void fma2(unsigned long long &d, unsigned long long a, unsigned long long b) {
    asm("fma.rn.f32x2 %0, %1, %2, %0;" : "+l"(d) : "l"(a), "l"(b));
}
__device__ __forceinline__ unsigned long long pack2(float x) {
    unsigned long long r;
    unsigned int u = __float_as_uint(x);
    asm("mov.b64 %0, {%1, %1};" : "=l"(r) : "r"(u));
    return r;
}

// ---------------------------------------------------------------------------
// K1: origin[b,c,p] = sum_k W[c,k] * inp[k->(f,c'), b, p]
// grid (HW/128, B), 128 threads. Per-thread tile: 8 channels x 8 pixels,
// accumulated as f32x2 pixel pairs (packed FMA doubles fp32 throughput).
// ---------------------------------------------------------------------------
#define TP 128
#define KC 32
__global__ __launch_bounds__(128) void k_origin(const float* __restrict__ inp,
                                                const float* __restrict__ origin_w) {
    __shared__ __align__(16) float xs[KC][TP];
    __shared__ float ws[KC][CC + 1];

    const int tid = threadIdx.x;
    const int b   = blockIdx.y;
    const int p0  = blockIdx.x * TP;
    const int ty  = tid >> 4;    // 0..7  -> channel group
    const int tx  = tid & 15;    // 0..15 -> pixel group
    const int c0  = ty * 8;
    const int pp0 = tx * 4;      // u64 pixel-pair base (pixels 8*tx .. 8*tx+7)

    unsigned long long acc[8][4];
#pragma unroll
    for (int i = 0; i < 8; i++)
#pragma unroll
        for (int j = 0; j < 4; j++) acc[i][j] = 0ull;

    for (int kc = 0; kc < KK; kc += KC) {
        // stage x tile: KC rows x TP pixels (coalesced float4)
#pragma unroll
        for (int it = 0; it < (KC * TP / 4) / 128; it++) {   // 8 iters
            int e = tid + it * 128;
            int row = e >> 5, col4 = e & 31;
            int k = kc + row;
            int f = k >> 6, cp = k & 63;
            const float4* g = (const float4*)(inp + (size_t)((f * BB + b) * CC + cp) * HW + p0);
            *(float4*)&xs[row][col4 * 4] = g[col4];
        }
        // stage W chunk (padded to kill bank conflicts on store)
#pragma unroll
        for (int it = 0; it < (KC * CC) / 128; it++) {       // 16 iters
            int e = it * 128 + tid;
            int cch = e >> 5, kkx = e & 31;
            ws[kkx][cch] = origin_w[cch * KK + kc + kkx];
        }
        __syncthreads();

#pragma unroll 8
        for (int kx = 0; kx < KC; kx++) {
            const unsigned long long* xrow = (const unsigned long long*)&xs[kx][0];
            ulonglong2 xa = *(const ulonglong2*)&xrow[pp0];
            ulonglong2 xb = *(const ulonglong2*)&xrow[pp0 + 2];
#pragma unroll
            for (int ci = 0; ci < 8; ci++) {
                unsigned long long ww = pack2(ws[kx][c0 + ci]);
                fma2(acc[ci][0], ww, xa.x);
                fma2(acc[ci][1], ww, xa.y);
                fma2(acc[ci][2], ww, xb.x);
                fma2(acc[ci][3], ww, xb.y);
            }
        }
        __syncthreads();
    }

#pragma unroll
    for (int ci = 0; ci < 8; ci++) {
        float* outp = g_origin + (size_t)(b * CC + c0 + ci) * HW + p0 + tx * 8;
        *(ulonglong2*)outp       = make_ulonglong2(acc[ci][0], acc[ci][1]);
        *((ulonglong2*)outp + 1) = make_ulonglong2(acc[ci][2], acc[ci][3]);
    }
}

// ---------------------------------------------------------------------------
// K2: per (b,c,f) reductions over 16384 pixels:
//   dot = sum origin*(last-inp_f), nrm = sum (last-inp_f)^2, ds = sum (last-inp_f)
// grid (C, B), 256 threads, fully coalesced float4 streams.
// ---------------------------------------------------------------------------
__global__ __launch_bounds__(256) void k_stats(const float* __restrict__ inp) {
    const int b = blockIdx.y, c = blockIdx.x, tid = threadIdx.x;
    const float4* last = (const float4*)(inp + (size_t)((4 * BB + b) * CC + c) * HW);
    const float4* org  = (const float4*)(g_origin + (size_t)(b * CC + c) * HW);
    const float4* fr0 = (const float4*)(inp + (size_t)((0 * BB + b) * CC + c) * HW);
    const float4* fr1 = (const float4*)(inp + (size_t)((1 * BB + b) * CC + c) * HW);
    const float4* fr2 = (const float4*)(inp + (size_t)((2 * BB + b) * CC + c) * HW);
    const float4* fr3 = (const float4*)(inp + (size_t)((3 * BB + b) * CC + c) * HW);
    const float4* frs[4] = {fr0, fr1, fr2, fr3};

    float dot[4] = {0.f, 0.f, 0.f, 0.f};
    float nrm[4] = {0.f, 0.f, 0.f, 0.f};
    float dsm[4] = {0.f, 0.f, 0.f, 0.f};

    for (int i = tid; i < HW / 4; i += 256) {
        float4 l = last[i], o = org[i];
#pragma unroll
        for (int f = 0; f < 4; f++) {
            float4 x = frs[f][i];
            float d0 = l.x - x.x, d1 = l.y - x.y, d2 = l.z - x.z, d3 = l.w - x.w;
            dot[f] += o.x * d0 + o.y * d1 + o.z * d2 + o.w * d3;
            nrm[f] += d0 * d0 + d1 * d1 + d2 * d2 + d3 * d3;
            dsm[f] += d0 + d1 + d2 + d3;
        }
    }

    float v[12];
#pragma unroll
    for (int f = 0; f < 4; f++) { v[f] = dot[f]; v[4 + f] = nrm[f]; v[8 + f] = dsm[f]; }

    const int lane = tid & 31, warp = tid >> 5;
#pragma unroll
    for (int s = 0; s < 12; s++)
#pragma unroll
        for (int o = 16; o > 0; o >>= 1)
            v[s] += __shfl_down_sync(0xffffffffu, v[s], o);

    __shared__ float red[8][12];
    if (lane == 0) {
#pragma unroll
        for (int s = 0; s < 12; s++) red[warp][s] = v[s];
    }
    __syncthreads();
    if (tid < 12) {
        float s = 0.f;
#pragma unroll
        for (int w = 0; w < 8; w++) s += red[w][tid];
        g_stats[(b * CC + c) * 12 + tid] = s;
    }
}

// ---------------------------------------------------------------------------
// K3: coefficients + fold out_w/origin_b into per-(b,f,c) GEMV weights A.
//   coef = (dot + ob[c]*ds) / max(sqrt(nrm),1e-12)^2
//   A[b,f,c] = -w1[c]*coef_f (f<4);  A[b,4,c] = w2[c] + w1[c]*sum_f coef_f
// ---------------------------------------------------------------------------
__global__ void k_coef(const float* __restrict__ origin_b,
                       const float* __restrict__ out_w) {
    int tid = threadIdx.x;
    if (tid >= BB * CC) return;
    int b = tid >> 6, c = tid & 63;
    float w1 = out_w[c], w2 = out_w[CC + c], ob = origin_b[c];
    const float* st = g_stats + (b * CC + c) * 12;
    float ssum = 0.f;
#pragma unroll
    for (int f = 0; f < 4; f++) {
        float dt   = st[f] + ob * st[8 + f];
        float nn   = sqrtf(st[4 + f]);
        float den  = fmaxf(nn, 1e-12f);
        float coef = dt / (den * den);
        g_A[(b * NFR + f) * CC + c] = -w1 * coef;
        ssum += coef;
    }
    g_A[(b * NFR + 4) * CC + c] = w2 + w1 * ssum;
}

// ---------------------------------------------------------------------------
// K4: y[b,p] = sum_{k=0..319} A[b,k] * inp[k,b,p] + out_b   (memory bound)
// grid (HW/512, B), 128 threads, 4 pixels (float4) per thread.
// ---------------------------------------------------------------------------
__global__ __launch_bounds__(128) void k_final(const float* __restrict__ inp,
                                               const float* __restrict__ out_b,
                                               float* __restrict__ y) {
    __shared__ float sA[KK];
    const int b = blockIdx.y, tid = threadIdx.x;
    for (int i = tid; i < KK; i += 128) sA[i] = g_A[b * KK + i];
    __syncthreads();

    const int p = blockIdx.x * 512 + tid * 4;
    float ob = out_b[0];
    float4 acc = make_float4(ob, ob, ob, ob);
#pragma unroll 8
    for (int k = 0; k < KK; k++) {
        int f = k >> 6, c = k & 63;
        const float4 v = *(const float4*)(inp + (size_t)((f * BB + b) * CC + c) * HW + p);
        float a = sA[k];
        acc.x += a * v.x; acc.y += a * v.y; acc.z += a * v.z; acc.w += a * v.w;
    }
    *(float4*)(y + (size_t)b * HW + p) = acc;
}

// ---------------------------------------------------------------------------
extern "C" void kernel_launch(void* const* d_in, const int* in_sizes, int n_in,
                              void* d_out, int out_size) {
    const float* inp      = (const float*)d_in[0];
    const float* origin_w = (const float*)d_in[1];
    const float* origin_b = (const float*)d_in[2];
    const float* out_w    = (const float*)d_in[3];
    const float* out_b    = (const float*)d_in[4];
    float* y = (float*)d_out;

    k_origin<<<dim3(HW / TP, BB), 128>>>(inp, origin_w);
    k_stats <<<dim3(CC, BB), 256>>>(inp);
    k_coef  <<<1, 512>>>(origin_b, out_w);
    k_final <<<dim3(HW / 512, BB), 128>>>(inp, out_b, y);
}